// round 6
// baseline (speedup 1.0000x reference)
#include <cuda_runtime.h>
#include <cuda_fp16.h>

#define N_T1 168            // dow(7) * sex(2) * month(12)
#define N_T2 744            // time(24) * day(31)
#define N_T3 100            // age
#define NE   (N_T1 + N_T2 + N_T3)   // 1012

// Table layout (halves):
//  T1 dup : entries 0..167, 64 halves each (copy A at +0, copy B at +32)
//  T3 dup : at half-offset 10752, 100 entries x 64 halves
//  T2 one : at half-offset 17152, 744 entries x 32 halves (single copy)
// Total = 40960 halves = 81,920 B
#define T3_OFF_B 21504      // 168*128
#define T2_OFF_B 34304      // 21504 + 100*128
#define TAB_UINT4 5120      // 81920 / 16

__device__ uint4 g_tab[TAB_UINT4];

__global__ void precompute_kernel(const float* __restrict__ emb_dow,
                                  const float* __restrict__ emb_time,
                                  const float* __restrict__ emb_sex,
                                  const float* __restrict__ emb_age,
                                  const float* __restrict__ emb_month,
                                  const float* __restrict__ emb_day,
                                  const float* __restrict__ W,
                                  const float* __restrict__ b) {
    int t = blockIdx.x * blockDim.x + threadIdx.x;
    if (t >= NE * 32) return;
    int e = t >> 5;
    int f = t & 31;
    float v = 0.f;
    __half* g = reinterpret_cast<__half*>(g_tab);
    // W row layout follows concat order: dow[0:4) time[4:8) sex[8:12) age[12:16) month[16:20) day[20:24)
    if (e < N_T1) {
        int d = e / 24, rem = e % 24;
        int s = rem / 12, m = rem % 12;
        #pragma unroll
        for (int j = 0; j < 4; j++) {
            v = fmaf(emb_dow[d * 4 + j],   W[(0 + j) * 32 + f], v);
            v = fmaf(emb_sex[s * 4 + j],   W[(8 + j) * 32 + f], v);
            v = fmaf(emb_month[m * 4 + j], W[(16 + j) * 32 + f], v);
        }
        __half hv = __float2half_rn(v);
        g[e * 64 + f] = hv;           // copy A (banks 0..15)
        g[e * 64 + 32 + f] = hv;      // copy B (banks 16..31)
    } else if (e < N_T1 + N_T2) {
        int e2 = e - N_T1;
        int tm = e2 / 31, dy = e2 % 31;
        #pragma unroll
        for (int j = 0; j < 4; j++) {
            v = fmaf(emb_time[tm * 4 + j], W[(4 + j) * 32 + f], v);
            v = fmaf(emb_day[dy * 4 + j],  W[(20 + j) * 32 + f], v);
        }
        g[(T2_OFF_B / 2) + e2 * 32 + f] = __float2half_rn(v);   // single copy
    } else {
        int a = e - (N_T1 + N_T2);
        v = b[f];
        #pragma unroll
        for (int j = 0; j < 4; j++)
            v = fmaf(emb_age[a * 4 + j], W[(12 + j) * 32 + f], v);
        __half hv = __float2half_rn(v);
        g[(T3_OFF_B / 2) + a * 64 + f] = hv;        // copy A
        g[(T3_OFF_B / 2) + a * 64 + 32 + f] = hv;   // copy B
    }
}

__global__ __launch_bounds__(768, 2)
void mf_main_kernel(const int* __restrict__ dow,
                    const int* __restrict__ tim,
                    const int* __restrict__ sex,
                    const int* __restrict__ age,
                    const int* __restrict__ month,
                    const int* __restrict__ day,
                    const int* __restrict__ dest,
                    const float4* __restrict__ item4,
                    float* __restrict__ out,
                    int n) {
    extern __shared__ uint4 sp[];   // 5120 uint4 = 81,920 B
    for (int i = threadIdx.x; i < TAB_UINT4; i += blockDim.x)
        sp[i] = g_tab[i];
    __syncthreads();

    const char* spb = reinterpret_cast<const char*>(sp);

    const int lane = threadIdx.x & 31;
    const int warp = threadIdx.x >> 5;
    const int sub  = lane & 7;        // position within 8-lane group
    const int grp  = lane >> 3;       // group id 0..3
    // Dup tables: odd groups read copy B (banks 16..31), even groups copy A.
    const int par  = (grp & 1) * 64 + sub * 8;

    const int warpsTotal = gridDim.x * (blockDim.x >> 5);
    const int gwarp = blockIdx.x * (blockDim.x >> 5) + warp;

    for (int base = gwarp * 32; base < n; base += warpsTotal * 32) {
        // Phase A: coalesced per-lane index loads; pack 3 table indices into one int.
        int r = base + lane;
        int pk = 0, dd = 0;
        if (r < n) {
            int i1 = dow[r] * 24 + sex[r] * 12 + month[r];   // 0..167  (8 bits)
            int t2 = tim[r] * 31 + day[r];                   // 0..743  (10 bits)
            int a3 = age[r];                                 // 0..99   (7 bits)
            pk = i1 | (t2 << 8) | (a3 << 18);
            dd = dest[r];
        }

        // Phase B: 8 sub-iterations; each processes 4 rows with 8 lanes/row.
        #pragma unroll
        for (int s = 0; s < 8; s++) {
            int src = s * 4 + grp;
            int pks = __shfl_sync(0xffffffffu, pk, src);
            int dds = __shfl_sync(0xffffffffu, dd, src);
            int j1 = pks & 255;
            int j2 = (pks >> 8) & 1023;
            int j3 = (pks >> 18) & 127;

            // Longest-latency load first: 8 lanes x 16 B = one 128B item row.
            float4 v = __ldg(item4 + (size_t)dds * 8 + sub);

            // T1/T3 dup -> conflict-free; T2 single copy (expected 1.5x replay).
            uint2 A = *reinterpret_cast<const uint2*>(spb + j1 * 128 + par);
            uint2 C = *reinterpret_cast<const uint2*>(spb + T2_OFF_B + j2 * 64 + sub * 8);
            uint2 E = *reinterpret_cast<const uint2*>(spb + T3_OFF_B + j3 * 128 + par);

            // Sum the three table slices in packed fp16 (4 HADD2).
            __half2 s0 = __hadd2(__hadd2(*reinterpret_cast<const __half2*>(&A.x),
                                         *reinterpret_cast<const __half2*>(&C.x)),
                                 *reinterpret_cast<const __half2*>(&E.x));
            __half2 s1 = __hadd2(__hadd2(*reinterpret_cast<const __half2*>(&A.y),
                                         *reinterpret_cast<const __half2*>(&C.y)),
                                 *reinterpret_cast<const __half2*>(&E.y));

            float2 f0 = __half22float2(s0);
            float2 f1 = __half22float2(s1);

            float p;
            p =           f0.x * v.x;
            p = fmaf(f0.y, v.y, p);
            p = fmaf(f1.x, v.z, p);
            p = fmaf(f1.y, v.w, p);

            // Reduce across the 8-lane group.
            p += __shfl_xor_sync(0xffffffffu, p, 4);
            p += __shfl_xor_sync(0xffffffffu, p, 2);
            p += __shfl_xor_sync(0xffffffffu, p, 1);

            int row = base + src;
            if (sub == 0 && row < n)
                out[row] = p;
        }
    }
}

extern "C" void kernel_launch(void* const* d_in, const int* in_sizes, int n_in,
                              void* d_out, int out_size) {
    // Input order: dayofweek, time, sex, age, month, day, destination,
    // emb_dow, emb_time, emb_sex, emb_age, emb_month, emb_day, W, b, item_table
    const int* dow   = (const int*)d_in[0];
    const int* tim   = (const int*)d_in[1];
    const int* sex   = (const int*)d_in[2];
    const int* age   = (const int*)d_in[3];
    const int* month = (const int*)d_in[4];
    const int* day   = (const int*)d_in[5];
    const int* dest  = (const int*)d_in[6];
    const float* emb_dow   = (const float*)d_in[7];
    const float* emb_time  = (const float*)d_in[8];
    const float* emb_sex   = (const float*)d_in[9];
    const float* emb_age   = (const float*)d_in[10];
    const float* emb_month = (const float*)d_in[11];
    const float* emb_day   = (const float*)d_in[12];
    const float* W = (const float*)d_in[13];
    const float* b = (const float*)d_in[14];
    const float4* item4 = (const float4*)d_in[15];
    float* out = (float*)d_out;
    int n = in_sizes[0];

    // 1) Build fused pre-projected fp16 tables (T1/T3 duplicated, T2 single).
    int pre_threads = NE * 32;
    precompute_kernel<<<(pre_threads + 255) / 256, 256>>>(
        emb_dow, emb_time, emb_sex, emb_age, emb_month, emb_day, W, b);

    // 2) Main gather + dot kernel. 81,920 B dynamic smem, 2 CTAs/SM.
    int smem_bytes = TAB_UINT4 * (int)sizeof(uint4);
    cudaFuncSetAttribute(mf_main_kernel,
                         cudaFuncAttributeMaxDynamicSharedMemorySize, smem_bytes);
    mf_main_kernel<<<304, 768, smem_bytes>>>(
        dow, tim, sex, age, month, day, dest, item4, out, n);
}

// round 7
// speedup vs baseline: 1.0417x; 1.0417x over previous
#include <cuda_runtime.h>
#include <cuda_fp16.h>

#define N_T1 168            // dow(7) * sex(2) * month(12)
#define N_T2 744            // time(24) * day(31)
#define N_T3 100            // age
#define NE   (N_T1 + N_T2 + N_T3)   // 1012

// Pre-projected fused tables in fp16, DUPLICATED per entry:
// entry e occupies 128 B: copy A at [e*128, e*128+64)    -> smem banks 0..15
//                         copy B at [e*128+64, e*128+128) -> smem banks 16..31
__device__ uint4 g_projh[NE * 8];   // NE * 128 B

__global__ void precompute_kernel(const float* __restrict__ emb_dow,
                                  const float* __restrict__ emb_time,
                                  const float* __restrict__ emb_sex,
                                  const float* __restrict__ emb_age,
                                  const float* __restrict__ emb_month,
                                  const float* __restrict__ emb_day,
                                  const float* __restrict__ W,
                                  const float* __restrict__ b) {
    int t = blockIdx.x * blockDim.x + threadIdx.x;
    if (t >= NE * 32) return;
    int e = t >> 5;
    int f = t & 31;
    float v = 0.f;
    // W row layout follows concat order: dow[0:4) time[4:8) sex[8:12) age[12:16) month[16:20) day[20:24)
    if (e < N_T1) {
        int d = e / 24, rem = e % 24;
        int s = rem / 12, m = rem % 12;
        #pragma unroll
        for (int j = 0; j < 4; j++) {
            v = fmaf(emb_dow[d * 4 + j],   W[(0 + j) * 32 + f], v);
            v = fmaf(emb_sex[s * 4 + j],   W[(8 + j) * 32 + f], v);
            v = fmaf(emb_month[m * 4 + j], W[(16 + j) * 32 + f], v);
        }
    } else if (e < N_T1 + N_T2) {
        int e2 = e - N_T1;
        int tm = e2 / 31, dy = e2 % 31;
        #pragma unroll
        for (int j = 0; j < 4; j++) {
            v = fmaf(emb_time[tm * 4 + j], W[(4 + j) * 32 + f], v);
            v = fmaf(emb_day[dy * 4 + j],  W[(20 + j) * 32 + f], v);
        }
    } else {
        int a = e - (N_T1 + N_T2);
        v = b[f];
        #pragma unroll
        for (int j = 0; j < 4; j++)
            v = fmaf(emb_age[a * 4 + j], W[(12 + j) * 32 + f], v);
    }
    __half hv = __float2half_rn(v);
    __half* base = reinterpret_cast<__half*>(g_projh) + e * 64;
    base[f]      = hv;   // copy A
    base[32 + f] = hv;   // copy B
}

__global__ __launch_bounds__(1024, 1)
void mf_main_kernel(const int* __restrict__ dow,
                    const int* __restrict__ tim,
                    const int* __restrict__ sex,
                    const int* __restrict__ age,
                    const int* __restrict__ month,
                    const int* __restrict__ day,
                    const int* __restrict__ dest,
                    const float4* __restrict__ item4,
                    float* __restrict__ out,
                    int n) {
    extern __shared__ uint4 sp[];   // NE * 8 uint4 = 129,536 B (duplicated entries)
    for (int i = threadIdx.x; i < NE * 8; i += blockDim.x)
        sp[i] = g_projh[i];
    __syncthreads();

    const char* spb = reinterpret_cast<const char*>(sp);

    const int lane = threadIdx.x & 31;
    const int warp = threadIdx.x >> 5;
    const int sub  = lane & 7;        // position within 8-lane group
    const int grp  = lane >> 3;       // group id 0..3
    // Odd groups read copy B (banks 16..31), even groups copy A (banks 0..15):
    // half-warp LDS phases are deterministically conflict-free.
    const int par  = (grp & 1) * 64 + sub * 8;

    const int warpsTotal = gridDim.x * (blockDim.x >> 5);
    const int gwarp = blockIdx.x * (blockDim.x >> 5) + warp;

    for (int base = gwarp * 32; base < n; base += warpsTotal * 32) {
        // Phase A: coalesced per-lane index loads; pack 3 table indices into one int.
        int r = base + lane;
        int pk = 0, dd = 0;
        if (r < n) {
            int i1 = dow[r] * 24 + sex[r] * 12 + month[r];   // 0..167  (8 bits)
            int t2 = tim[r] * 31 + day[r];                   // 0..743  (10 bits)
            int a3 = age[r];                                 // 0..99   (7 bits)
            pk = i1 | (t2 << 8) | (a3 << 18);
            dd = dest[r];
        }

        // Prologue of the software pipeline: indices + item load for s=0.
        int pks = __shfl_sync(0xffffffffu, pk, grp);
        int dds = __shfl_sync(0xffffffffu, dd, grp);
        float4 v = __ldg(item4 + (size_t)dds * 8 + sub);

        // Phase B: 8 sub-iterations; each processes 4 rows with 8 lanes/row.
        // Item LDG for s+1 is issued before consuming s (depth-2 pipeline).
        #pragma unroll
        for (int s = 0; s < 8; s++) {
            int j1 = pks & 255;
            int j2 = N_T1 + ((pks >> 8) & 1023);
            int j3 = N_T1 + N_T2 + ((pks >> 18) & 127);

            // Prefetch next iteration: indices then the long-latency item load.
            float4 vn;
            if (s < 7) {
                pks = __shfl_sync(0xffffffffu, pk, (s + 1) * 4 + grp);
                int ddn = __shfl_sync(0xffffffffu, dd, (s + 1) * 4 + grp);
                vn = __ldg(item4 + (size_t)ddn * 8 + sub);
            }

            // Each lane reads 8 B (4 halves) of its row's entry; conflict-free.
            uint2 A = *reinterpret_cast<const uint2*>(spb + j1 * 128 + par);
            uint2 C = *reinterpret_cast<const uint2*>(spb + j2 * 128 + par);
            uint2 E = *reinterpret_cast<const uint2*>(spb + j3 * 128 + par);

            // Sum the three table slices in packed fp16 (4 HADD2).
            __half2 s0 = __hadd2(__hadd2(*reinterpret_cast<const __half2*>(&A.x),
                                         *reinterpret_cast<const __half2*>(&C.x)),
                                 *reinterpret_cast<const __half2*>(&E.x));
            __half2 s1 = __hadd2(__hadd2(*reinterpret_cast<const __half2*>(&A.y),
                                         *reinterpret_cast<const __half2*>(&C.y)),
                                 *reinterpret_cast<const __half2*>(&E.y));

            float2 f0 = __half22float2(s0);
            float2 f1 = __half22float2(s1);

            float p;
            p =           f0.x * v.x;
            p = fmaf(f0.y, v.y, p);
            p = fmaf(f1.x, v.z, p);
            p = fmaf(f1.y, v.w, p);

            // Reduce across the 8-lane group.
            p += __shfl_xor_sync(0xffffffffu, p, 4);
            p += __shfl_xor_sync(0xffffffffu, p, 2);
            p += __shfl_xor_sync(0xffffffffu, p, 1);

            int row = base + s * 4 + grp;
            if (sub == 0 && row < n)
                out[row] = p;

            v = vn;   // rotate the pipeline
        }
    }
}

extern "C" void kernel_launch(void* const* d_in, const int* in_sizes, int n_in,
                              void* d_out, int out_size) {
    // Input order: dayofweek, time, sex, age, month, day, destination,
    // emb_dow, emb_time, emb_sex, emb_age, emb_month, emb_day, W, b, item_table
    const int* dow   = (const int*)d_in[0];
    const int* tim   = (const int*)d_in[1];
    const int* sex   = (const int*)d_in[2];
    const int* age   = (const int*)d_in[3];
    const int* month = (const int*)d_in[4];
    const int* day   = (const int*)d_in[5];
    const int* dest  = (const int*)d_in[6];
    const float* emb_dow   = (const float*)d_in[7];
    const float* emb_time  = (const float*)d_in[8];
    const float* emb_sex   = (const float*)d_in[9];
    const float* emb_age   = (const float*)d_in[10];
    const float* emb_month = (const float*)d_in[11];
    const float* emb_day   = (const float*)d_in[12];
    const float* W = (const float*)d_in[13];
    const float* b = (const float*)d_in[14];
    const float4* item4 = (const float4*)d_in[15];
    float* out = (float*)d_out;
    int n = in_sizes[0];

    // 1) Build fused pre-projected fp16 tables (1012 x 32, duplicated per entry).
    int pre_threads = NE * 32;
    precompute_kernel<<<(pre_threads + 255) / 256, 256>>>(
        emb_dow, emb_time, emb_sex, emb_age, emb_month, emb_day, W, b);

    // 2) Main gather + dot kernel. 129,536 B dynamic smem -> opt-in required.
    int smem_bytes = NE * 8 * (int)sizeof(uint4);
    cudaFuncSetAttribute(mf_main_kernel,
                         cudaFuncAttributeMaxDynamicSharedMemorySize, smem_bytes);
    mf_main_kernel<<<152, 1024, smem_bytes>>>(
        dow, tim, sex, age, month, day, dest, item4, out, n);
}

// round 8
// speedup vs baseline: 1.0967x; 1.0528x over previous
#include <cuda_runtime.h>
#include <cuda_fp16.h>

#define N_T1 168            // dow(7) * sex(2) * month(12)
#define N_T2 744            // time(24) * day(31)
#define N_T3 100            // age
#define NE   (N_T1 + N_T2 + N_T3)   // 1012
#define NUM_DEST 100000

// Pre-projected fused tables in fp16, DUPLICATED per entry:
// entry e occupies 128 B: copy A at [e*128, e*128+64)    -> smem banks 0..15
//                         copy B at [e*128+64, e*128+128) -> smem banks 16..31
__device__ uint4 g_projh[NE * 8];        // NE * 128 B
// Item table converted to fp16: row = 32 halves = 64 B = 4 uint4.
__device__ uint4 g_itemh[NUM_DEST * 4];  // 6.4 MB

__global__ void precompute_kernel(const float* __restrict__ emb_dow,
                                  const float* __restrict__ emb_time,
                                  const float* __restrict__ emb_sex,
                                  const float* __restrict__ emb_age,
                                  const float* __restrict__ emb_month,
                                  const float* __restrict__ emb_day,
                                  const float* __restrict__ W,
                                  const float* __restrict__ b) {
    int t = blockIdx.x * blockDim.x + threadIdx.x;
    if (t >= NE * 32) return;
    int e = t >> 5;
    int f = t & 31;
    float v = 0.f;
    // W row layout follows concat order: dow[0:4) time[4:8) sex[8:12) age[12:16) month[16:20) day[20:24)
    if (e < N_T1) {
        int d = e / 24, rem = e % 24;
        int s = rem / 12, m = rem % 12;
        #pragma unroll
        for (int j = 0; j < 4; j++) {
            v = fmaf(emb_dow[d * 4 + j],   W[(0 + j) * 32 + f], v);
            v = fmaf(emb_sex[s * 4 + j],   W[(8 + j) * 32 + f], v);
            v = fmaf(emb_month[m * 4 + j], W[(16 + j) * 32 + f], v);
        }
    } else if (e < N_T1 + N_T2) {
        int e2 = e - N_T1;
        int tm = e2 / 31, dy = e2 % 31;
        #pragma unroll
        for (int j = 0; j < 4; j++) {
            v = fmaf(emb_time[tm * 4 + j], W[(4 + j) * 32 + f], v);
            v = fmaf(emb_day[dy * 4 + j],  W[(20 + j) * 32 + f], v);
        }
    } else {
        int a = e - (N_T1 + N_T2);
        v = b[f];
        #pragma unroll
        for (int j = 0; j < 4; j++)
            v = fmaf(emb_age[a * 4 + j], W[(12 + j) * 32 + f], v);
    }
    __half hv = __float2half_rn(v);
    __half* base = reinterpret_cast<__half*>(g_projh) + e * 64;
    base[f]      = hv;   // copy A
    base[32 + f] = hv;   // copy B
}

__global__ void convert_item_kernel(const float2* __restrict__ item2) {
    // One thread per half2 (2 floats): NUM_DEST*16 threads.
    int t = blockIdx.x * blockDim.x + threadIdx.x;
    if (t >= NUM_DEST * 16) return;
    float2 f = item2[t];
    reinterpret_cast<__half2*>(g_itemh)[t] = __floats2half2_rn(f.x, f.y);
}

__global__ __launch_bounds__(1024, 1)
void mf_main_kernel(const int* __restrict__ dow,
                    const int* __restrict__ tim,
                    const int* __restrict__ sex,
                    const int* __restrict__ age,
                    const int* __restrict__ month,
                    const int* __restrict__ day,
                    const int* __restrict__ dest,
                    float* __restrict__ out,
                    int n) {
    extern __shared__ uint4 sp[];   // NE * 8 uint4 = 129,536 B (duplicated entries)
    for (int i = threadIdx.x; i < NE * 8; i += blockDim.x)
        sp[i] = g_projh[i];
    __syncthreads();

    const char* spb = reinterpret_cast<const char*>(sp);

    const int lane = threadIdx.x & 31;
    const int warp = threadIdx.x >> 5;
    const int sub  = lane & 3;        // position within 4-lane group (8 halves each)
    const int grp  = lane >> 2;       // group id 0..7 (contiguous lanes)
    // Dup tables: adjacent groups have opposite parity -> each 8-lane LDS phase
    // hits disjoint bank halves: deterministically conflict-free.
    const int par  = (grp & 1) * 64 + sub * 16;

    const int warpsTotal = gridDim.x * (blockDim.x >> 5);
    const int gwarp = blockIdx.x * (blockDim.x >> 5) + warp;

    for (int base = gwarp * 32; base < n; base += warpsTotal * 32) {
        // Phase A: coalesced per-lane index loads; pack 3 table indices into one int.
        int r = base + lane;
        int pk = 0, dd = 0;
        if (r < n) {
            int i1 = dow[r] * 24 + sex[r] * 12 + month[r];   // 0..167  (8 bits)
            int t2 = tim[r] * 31 + day[r];                   // 0..743  (10 bits)
            int a3 = age[r];                                 // 0..99   (7 bits)
            pk = i1 | (t2 << 8) | (a3 << 18);
            dd = dest[r];
        }

        // Phase B: 4 sub-iterations; each processes 8 rows with 4 lanes/row.
        #pragma unroll
        for (int s = 0; s < 4; s++) {
            int src = s * 8 + grp;
            int pks = __shfl_sync(0xffffffffu, pk, src);
            int dds = __shfl_sync(0xffffffffu, dd, src);
            int j1 = pks & 255;
            int j2 = N_T1 + ((pks >> 8) & 1023);
            int j3 = N_T1 + N_T2 + ((pks >> 18) & 127);

            // Item row (fp16, 64 B): 4 lanes x 16 B. One line per row.
            uint4 V = __ldg(&g_itemh[(size_t)dds * 4 + sub]);

            // Table entries: each lane reads 16 B (8 halves); conflict-free.
            uint4 A = *reinterpret_cast<const uint4*>(spb + j1 * 128 + par);
            uint4 C = *reinterpret_cast<const uint4*>(spb + j2 * 128 + par);
            uint4 E = *reinterpret_cast<const uint4*>(spb + j3 * 128 + par);

            const __half2* a2 = reinterpret_cast<const __half2*>(&A);
            const __half2* c2 = reinterpret_cast<const __half2*>(&C);
            const __half2* e2 = reinterpret_cast<const __half2*>(&E);
            const __half2* v2 = reinterpret_cast<const __half2*>(&V);

            float p = 0.f;
            #pragma unroll
            for (int q = 0; q < 4; q++) {
                __half2 u = __hadd2(__hadd2(a2[q], c2[q]), e2[q]);
                float2 uf = __half22float2(u);
                float2 vf = __half22float2(v2[q]);
                p = fmaf(uf.x, vf.x, p);
                p = fmaf(uf.y, vf.y, p);
            }

            // Reduce across the 4-lane group (contiguous lanes).
            p += __shfl_xor_sync(0xffffffffu, p, 2);
            p += __shfl_xor_sync(0xffffffffu, p, 1);

            int row = base + src;
            if (sub == 0 && row < n)
                out[row] = p;     // 8 consecutive rows per step: 1 wavefront
        }
    }
}

extern "C" void kernel_launch(void* const* d_in, const int* in_sizes, int n_in,
                              void* d_out, int out_size) {
    // Input order: dayofweek, time, sex, age, month, day, destination,
    // emb_dow, emb_time, emb_sex, emb_age, emb_month, emb_day, W, b, item_table
    const int* dow   = (const int*)d_in[0];
    const int* tim   = (const int*)d_in[1];
    const int* sex   = (const int*)d_in[2];
    const int* age   = (const int*)d_in[3];
    const int* month = (const int*)d_in[4];
    const int* day   = (const int*)d_in[5];
    const int* dest  = (const int*)d_in[6];
    const float* emb_dow   = (const float*)d_in[7];
    const float* emb_time  = (const float*)d_in[8];
    const float* emb_sex   = (const float*)d_in[9];
    const float* emb_age   = (const float*)d_in[10];
    const float* emb_month = (const float*)d_in[11];
    const float* emb_day   = (const float*)d_in[12];
    const float* W = (const float*)d_in[13];
    const float* b = (const float*)d_in[14];
    const float2* item2 = (const float2*)d_in[15];
    float* out = (float*)d_out;
    int n = in_sizes[0];

    // 1) Build fused pre-projected fp16 tables (1012 x 32, duplicated per entry).
    int pre_threads = NE * 32;
    precompute_kernel<<<(pre_threads + 255) / 256, 256>>>(
        emb_dow, emb_time, emb_sex, emb_age, emb_month, emb_day, W, b);

    // 1b) Convert item table to fp16 (NUM_DEST x 32).
    int cv_threads = NUM_DEST * 16;
    convert_item_kernel<<<(cv_threads + 255) / 256, 256>>>(item2);

    // 2) Main gather + dot kernel. 129,536 B dynamic smem -> opt-in required.
    int smem_bytes = NE * 8 * (int)sizeof(uint4);
    cudaFuncSetAttribute(mf_main_kernel,
                         cudaFuncAttributeMaxDynamicSharedMemorySize, smem_bytes);
    mf_main_kernel<<<152, 1024, smem_bytes>>>(
        dow, tim, sex, age, month, day, dest, out, n);
}

// round 9
// speedup vs baseline: 1.1550x; 1.0531x over previous
#include <cuda_runtime.h>
#include <cuda_fp16.h>

#define N_T1 168            // dow(7) * sex(2) * month(12)
#define N_T2 744            // time(24) * day(31)
#define N_T3 100            // age
#define NE   (N_T1 + N_T2 + N_T3)   // 1012
#define NUM_DEST 100000

// Pre-projected fused tables in fp16, DUPLICATED per entry:
// entry e occupies 128 B: copy A at [e*128, e*128+64)    -> smem banks 0..15
//                         copy B at [e*128+64, e*128+128) -> smem banks 16..31
__device__ uint4 g_projh[NE * 8];        // NE * 128 B
// Item table converted to fp16: row = 32 halves = 64 B = 4 uint4.
__device__ uint4 g_itemh[NUM_DEST * 4];  // 6.4 MB

// Fused prep kernel: blocks [0, CV_BLOCKS) convert the item table (bandwidth-
// bound), blocks [CV_BLOCKS, ...) build the projected tables (latency-bound).
// Running them in one launch overlaps the two instead of serializing launches.
#define CV_THREADS (NUM_DEST * 16)
#define CV_BLOCKS  ((CV_THREADS + 255) / 256)
#define PRE_THREADS (NE * 32)
#define PRE_BLOCKS ((PRE_THREADS + 255) / 256)

__global__ __launch_bounds__(256)
void prep_kernel(const float* __restrict__ emb_dow,
                 const float* __restrict__ emb_time,
                 const float* __restrict__ emb_sex,
                 const float* __restrict__ emb_age,
                 const float* __restrict__ emb_month,
                 const float* __restrict__ emb_day,
                 const float* __restrict__ W,
                 const float* __restrict__ b,
                 const float2* __restrict__ item2) {
    if (blockIdx.x < CV_BLOCKS) {
        // ---- Item table fp32 -> fp16 (one thread per half2) ----
        int t = blockIdx.x * 256 + threadIdx.x;
        if (t >= CV_THREADS) return;
        float2 f = item2[t];
        reinterpret_cast<__half2*>(g_itemh)[t] = __floats2half2_rn(f.x, f.y);
        return;
    }
    // ---- Pre-projected fused user tables ----
    int t = (blockIdx.x - CV_BLOCKS) * 256 + threadIdx.x;
    if (t >= PRE_THREADS) return;
    int e = t >> 5;
    int f = t & 31;
    float v = 0.f;
    // W row layout follows concat order: dow[0:4) time[4:8) sex[8:12) age[12:16) month[16:20) day[20:24)
    if (e < N_T1) {
        int d = e / 24, rem = e % 24;
        int s = rem / 12, m = rem % 12;
        #pragma unroll
        for (int j = 0; j < 4; j++) {
            v = fmaf(emb_dow[d * 4 + j],   W[(0 + j) * 32 + f], v);
            v = fmaf(emb_sex[s * 4 + j],   W[(8 + j) * 32 + f], v);
            v = fmaf(emb_month[m * 4 + j], W[(16 + j) * 32 + f], v);
        }
    } else if (e < N_T1 + N_T2) {
        int e2 = e - N_T1;
        int tm = e2 / 31, dy = e2 % 31;
        #pragma unroll
        for (int j = 0; j < 4; j++) {
            v = fmaf(emb_time[tm * 4 + j], W[(4 + j) * 32 + f], v);
            v = fmaf(emb_day[dy * 4 + j],  W[(20 + j) * 32 + f], v);
        }
    } else {
        int a = e - (N_T1 + N_T2);
        v = b[f];
        #pragma unroll
        for (int j = 0; j < 4; j++)
            v = fmaf(emb_age[a * 4 + j], W[(12 + j) * 32 + f], v);
    }
    __half hv = __float2half_rn(v);
    __half* base = reinterpret_cast<__half*>(g_projh) + e * 64;
    base[f]      = hv;   // copy A
    base[32 + f] = hv;   // copy B
}

__global__ __launch_bounds__(1024, 1)
void mf_main_kernel(const int* __restrict__ dow,
                    const int* __restrict__ tim,
                    const int* __restrict__ sex,
                    const int* __restrict__ age,
                    const int* __restrict__ month,
                    const int* __restrict__ day,
                    const int* __restrict__ dest,
                    float* __restrict__ out,
                    int n) {
    extern __shared__ uint4 sp[];   // NE * 8 uint4 = 129,536 B (duplicated entries)
    for (int i = threadIdx.x; i < NE * 8; i += blockDim.x)
        sp[i] = g_projh[i];
    __syncthreads();

    const char* spb = reinterpret_cast<const char*>(sp);

    const int lane = threadIdx.x & 31;
    const int warp = threadIdx.x >> 5;
    const int sub  = lane & 3;        // position within 4-lane group (8 halves each)
    const int grp  = lane >> 2;       // group id 0..7 (contiguous lanes)
    // Dup tables: adjacent groups have opposite parity -> each 8-lane LDS phase
    // hits disjoint bank halves: deterministically conflict-free.
    const int par  = (grp & 1) * 64 + sub * 16;

    const int warpsTotal = gridDim.x * (blockDim.x >> 5);
    const int gwarp = blockIdx.x * (blockDim.x >> 5) + warp;

    for (int base = gwarp * 32; base < n; base += warpsTotal * 32) {
        // Phase A: coalesced per-lane index loads; pack 3 table indices into one int.
        int r = base + lane;
        int pk = 0, dd = 0;
        if (r < n) {
            int i1 = dow[r] * 24 + sex[r] * 12 + month[r];   // 0..167  (8 bits)
            int t2 = tim[r] * 31 + day[r];                   // 0..743  (10 bits)
            int a3 = age[r];                                 // 0..99   (7 bits)
            pk = i1 | (t2 << 8) | (a3 << 18);
            dd = dest[r];
        }

        // Pipeline prologue: indices + item row for step 0.
        int pks = __shfl_sync(0xffffffffu, pk, grp);
        int dds = __shfl_sync(0xffffffffu, dd, grp);
        uint4 V = __ldg(&g_itemh[(size_t)dds * 4 + sub]);

        // Phase B: 4 sub-iterations; each processes 8 rows with 4 lanes/row.
        // Item LDG for step s+1 issues before step s is consumed (depth-2).
        #pragma unroll
        for (int s = 0; s < 4; s++) {
            int j1 = pks & 255;
            int j2 = N_T1 + ((pks >> 8) & 1023);
            int j3 = N_T1 + N_T2 + ((pks >> 18) & 127);

            uint4 Vn;
            if (s < 3) {
                pks = __shfl_sync(0xffffffffu, pk, (s + 1) * 8 + grp);
                int ddn = __shfl_sync(0xffffffffu, dd, (s + 1) * 8 + grp);
                Vn = __ldg(&g_itemh[(size_t)ddn * 4 + sub]);
            }

            // Table entries: each lane reads 16 B (8 halves); conflict-free.
            uint4 A = *reinterpret_cast<const uint4*>(spb + j1 * 128 + par);
            uint4 C = *reinterpret_cast<const uint4*>(spb + j2 * 128 + par);
            uint4 E = *reinterpret_cast<const uint4*>(spb + j3 * 128 + par);

            const __half2* a2 = reinterpret_cast<const __half2*>(&A);
            const __half2* c2 = reinterpret_cast<const __half2*>(&C);
            const __half2* e2 = reinterpret_cast<const __half2*>(&E);
            const __half2* v2 = reinterpret_cast<const __half2*>(&V);

            float p = 0.f;
            #pragma unroll
            for (int q = 0; q < 4; q++) {
                __half2 u = __hadd2(__hadd2(a2[q], c2[q]), e2[q]);
                float2 uf = __half22float2(u);
                float2 vf = __half22float2(v2[q]);
                p = fmaf(uf.x, vf.x, p);
                p = fmaf(uf.y, vf.y, p);
            }

            // Reduce across the 4-lane group (contiguous lanes).
            p += __shfl_xor_sync(0xffffffffu, p, 2);
            p += __shfl_xor_sync(0xffffffffu, p, 1);

            int row = base + s * 8 + grp;
            if (sub == 0 && row < n)
                out[row] = p;     // 8 consecutive rows per step: 1 wavefront

            V = Vn;   // rotate pipeline
        }
    }
}

extern "C" void kernel_launch(void* const* d_in, const int* in_sizes, int n_in,
                              void* d_out, int out_size) {
    // Input order: dayofweek, time, sex, age, month, day, destination,
    // emb_dow, emb_time, emb_sex, emb_age, emb_month, emb_day, W, b, item_table
    const int* dow   = (const int*)d_in[0];
    const int* tim   = (const int*)d_in[1];
    const int* sex   = (const int*)d_in[2];
    const int* age   = (const int*)d_in[3];
    const int* month = (const int*)d_in[4];
    const int* day   = (const int*)d_in[5];
    const int* dest  = (const int*)d_in[6];
    const float* emb_dow   = (const float*)d_in[7];
    const float* emb_time  = (const float*)d_in[8];
    const float* emb_sex   = (const float*)d_in[9];
    const float* emb_age   = (const float*)d_in[10];
    const float* emb_month = (const float*)d_in[11];
    const float* emb_day   = (const float*)d_in[12];
    const float* W = (const float*)d_in[13];
    const float* b = (const float*)d_in[14];
    const float2* item2 = (const float2*)d_in[15];
    float* out = (float*)d_out;
    int n = in_sizes[0];

    // 1) Fused prep: item fp16 conversion + projected-table build, one launch.
    prep_kernel<<<CV_BLOCKS + PRE_BLOCKS, 256>>>(
        emb_dow, emb_time, emb_sex, emb_age, emb_month, emb_day, W, b, item2);

    // 2) Main gather + dot kernel. 129,536 B dynamic smem -> opt-in required.
    int smem_bytes = NE * 8 * (int)sizeof(uint4);
    cudaFuncSetAttribute(mf_main_kernel,
                         cudaFuncAttributeMaxDynamicSharedMemorySize, smem_bytes);
    mf_main_kernel<<<152, 1024, smem_bytes>>>(
        dow, tim, sex, age, month, day, dest, out, n);
}

// round 10
// speedup vs baseline: 1.1560x; 1.0009x over previous
#include <cuda_runtime.h>
#include <cuda_fp16.h>

#define N_T1 168            // dow(7) * sex(2) * month(12)
#define N_T2 744            // time(24) * day(31)
#define N_T3 100            // age
#define NE   (N_T1 + N_T2 + N_T3)   // 1012
#define NUM_DEST 100000

// Pre-projected fused tables in fp16, DUPLICATED per entry:
// entry e occupies 128 B: copy A at [e*128, e*128+64)    -> smem banks 0..15
//                         copy B at [e*128+64, e*128+128) -> smem banks 16..31
__device__ uint4 g_projh[NE * 8];        // NE * 128 B
// Item table converted to fp16: row = 32 halves = 64 B = 4 uint4.
__device__ uint4 g_itemh[NUM_DEST * 4];  // 6.4 MB

// Fused prep kernel: blocks [0, CV_BLOCKS) convert the item table (bandwidth-
// bound), blocks [CV_BLOCKS, ...) build the projected tables (latency-bound).
#define CV_THREADS (NUM_DEST * 16)
#define CV_BLOCKS  ((CV_THREADS + 255) / 256)
#define PRE_THREADS (NE * 32)
#define PRE_BLOCKS ((PRE_THREADS + 255) / 256)

__global__ __launch_bounds__(256)
void prep_kernel(const float* __restrict__ emb_dow,
                 const float* __restrict__ emb_time,
                 const float* __restrict__ emb_sex,
                 const float* __restrict__ emb_age,
                 const float* __restrict__ emb_month,
                 const float* __restrict__ emb_day,
                 const float* __restrict__ W,
                 const float* __restrict__ b,
                 const float2* __restrict__ item2) {
    if (blockIdx.x < CV_BLOCKS) {
        // ---- Item table fp32 -> fp16 (one thread per half2) ----
        int t = blockIdx.x * 256 + threadIdx.x;
        if (t >= CV_THREADS) return;
        float2 f = item2[t];
        reinterpret_cast<__half2*>(g_itemh)[t] = __floats2half2_rn(f.x, f.y);
        return;
    }
    // ---- Pre-projected fused user tables ----
    int t = (blockIdx.x - CV_BLOCKS) * 256 + threadIdx.x;
    if (t >= PRE_THREADS) return;
    int e = t >> 5;
    int f = t & 31;
    float v = 0.f;
    // W row layout follows concat order: dow[0:4) time[4:8) sex[8:12) age[12:16) month[16:20) day[20:24)
    if (e < N_T1) {
        int d = e / 24, rem = e % 24;
        int s = rem / 12, m = rem % 12;
        #pragma unroll
        for (int j = 0; j < 4; j++) {
            v = fmaf(emb_dow[d * 4 + j],   W[(0 + j) * 32 + f], v);
            v = fmaf(emb_sex[s * 4 + j],   W[(8 + j) * 32 + f], v);
            v = fmaf(emb_month[m * 4 + j], W[(16 + j) * 32 + f], v);
        }
    } else if (e < N_T1 + N_T2) {
        int e2 = e - N_T1;
        int tm = e2 / 31, dy = e2 % 31;
        #pragma unroll
        for (int j = 0; j < 4; j++) {
            v = fmaf(emb_time[tm * 4 + j], W[(4 + j) * 32 + f], v);
            v = fmaf(emb_day[dy * 4 + j],  W[(20 + j) * 32 + f], v);
        }
    } else {
        int a = e - (N_T1 + N_T2);
        v = b[f];
        #pragma unroll
        for (int j = 0; j < 4; j++)
            v = fmaf(emb_age[a * 4 + j], W[(12 + j) * 32 + f], v);
    }
    __half hv = __float2half_rn(v);
    __half* base = reinterpret_cast<__half*>(g_projh) + e * 64;
    base[f]      = hv;   // copy A
    base[32 + f] = hv;   // copy B
}

__global__ __launch_bounds__(1024, 1)
void mf_main_kernel(const int* __restrict__ dow,
                    const int* __restrict__ tim,
                    const int* __restrict__ sex,
                    const int* __restrict__ age,
                    const int* __restrict__ month,
                    const int* __restrict__ day,
                    const int* __restrict__ dest,
                    float* __restrict__ out,
                    int n) {
    extern __shared__ uint4 sp[];   // table (NE*8 uint4) + per-warp idx staging
    int2* stage = reinterpret_cast<int2*>(sp + NE * 8);   // 32 warps x 32 int2 = 8 KB

    for (int i = threadIdx.x; i < NE * 8; i += blockDim.x)
        sp[i] = g_projh[i];
    __syncthreads();

    const char* spb = reinterpret_cast<const char*>(sp);

    const int lane = threadIdx.x & 31;
    const int warp = threadIdx.x >> 5;
    const int sub  = lane & 3;        // position within 4-lane group (8 halves each)
    const int grp  = lane >> 2;       // group id 0..7 (contiguous lanes)
    // Dup tables: adjacent groups have opposite parity -> each 8-lane LDS phase
    // hits disjoint bank halves: deterministically conflict-free.
    const int par  = (grp & 1) * 64 + sub * 16;

    int2* stw = stage + warp * 32;    // this warp's staging slots

    const int warpsTotal = gridDim.x * (blockDim.x >> 5);
    const int gwarp = blockIdx.x * (blockDim.x >> 5) + warp;

    for (int base = gwarp * 32; base < n; base += warpsTotal * 32) {
        // Phase A: coalesced per-lane index loads; pack + stage to smem.
        int r = base + lane;
        int pk = 0, dd = 0;
        if (r < n) {
            int i1 = dow[r] * 24 + sex[r] * 12 + month[r];   // 0..167  (8 bits)
            int t2 = tim[r] * 31 + day[r];                   // 0..743  (10 bits)
            int a3 = age[r];                                 // 0..99   (7 bits)
            pk = i1 | (t2 << 8) | (a3 << 18);
            dd = dest[r];
        }
        stw[lane] = make_int2(pk, dd);
        __syncwarp();

        // Batched broadcast reads: all 4 steps' (pk, dd) at once (no chains).
        int2 sd0 = stw[0 * 8 + grp];
        int2 sd1 = stw[1 * 8 + grp];
        int2 sd2 = stw[2 * 8 + grp];
        int2 sd3 = stw[3 * 8 + grp];

        // Batched item loads: 4 independent LDGs in flight (MLP=4).
        uint4 V0 = __ldg(&g_itemh[(size_t)sd0.y * 4 + sub]);
        uint4 V1 = __ldg(&g_itemh[(size_t)sd1.y * 4 + sub]);
        uint4 V2 = __ldg(&g_itemh[(size_t)sd2.y * 4 + sub]);
        uint4 V3 = __ldg(&g_itemh[(size_t)sd3.y * 4 + sub]);

        int pks[4] = {sd0.x, sd1.x, sd2.x, sd3.x};
        uint4 Vs[4] = {V0, V1, V2, V3};

        // Phase B: 4 sub-iterations; each processes 8 rows with 4 lanes/row.
        #pragma unroll
        for (int s = 0; s < 4; s++) {
            int j1 = pks[s] & 255;
            int j2 = N_T1 + ((pks[s] >> 8) & 1023);
            int j3 = N_T1 + N_T2 + ((pks[s] >> 18) & 127);

            // Table entries: each lane reads 16 B (8 halves); conflict-free.
            uint4 A = *reinterpret_cast<const uint4*>(spb + j1 * 128 + par);
            uint4 C = *reinterpret_cast<const uint4*>(spb + j2 * 128 + par);
            uint4 E = *reinterpret_cast<const uint4*>(spb + j3 * 128 + par);

            const __half2* a2 = reinterpret_cast<const __half2*>(&A);
            const __half2* c2 = reinterpret_cast<const __half2*>(&C);
            const __half2* e2 = reinterpret_cast<const __half2*>(&E);
            const __half2* v2 = reinterpret_cast<const __half2*>(&Vs[s]);

            float p = 0.f;
            #pragma unroll
            for (int q = 0; q < 4; q++) {
                __half2 u = __hadd2(__hadd2(a2[q], c2[q]), e2[q]);
                float2 uf = __half22float2(u);
                float2 vf = __half22float2(v2[q]);
                p = fmaf(uf.x, vf.x, p);
                p = fmaf(uf.y, vf.y, p);
            }

            // Reduce across the 4-lane group (contiguous lanes).
            p += __shfl_xor_sync(0xffffffffu, p, 2);
            p += __shfl_xor_sync(0xffffffffu, p, 1);

            int row = base + s * 8 + grp;
            if (sub == 0 && row < n)
                out[row] = p;     // 8 consecutive rows per step: 1 wavefront
        }
    }
}

extern "C" void kernel_launch(void* const* d_in, const int* in_sizes, int n_in,
                              void* d_out, int out_size) {
    // Input order: dayofweek, time, sex, age, month, day, destination,
    // emb_dow, emb_time, emb_sex, emb_age, emb_month, emb_day, W, b, item_table
    const int* dow   = (const int*)d_in[0];
    const int* tim   = (const int*)d_in[1];
    const int* sex   = (const int*)d_in[2];
    const int* age   = (const int*)d_in[3];
    const int* month = (const int*)d_in[4];
    const int* day   = (const int*)d_in[5];
    const int* dest  = (const int*)d_in[6];
    const float* emb_dow   = (const float*)d_in[7];
    const float* emb_time  = (const float*)d_in[8];
    const float* emb_sex   = (const float*)d_in[9];
    const float* emb_age   = (const float*)d_in[10];
    const float* emb_month = (const float*)d_in[11];
    const float* emb_day   = (const float*)d_in[12];
    const float* W = (const float*)d_in[13];
    const float* b = (const float*)d_in[14];
    const float2* item2 = (const float2*)d_in[15];
    float* out = (float*)d_out;
    int n = in_sizes[0];

    // 1) Fused prep: item fp16 conversion + projected-table build, one launch.
    prep_kernel<<<CV_BLOCKS + PRE_BLOCKS, 256>>>(
        emb_dow, emb_time, emb_sex, emb_age, emb_month, emb_day, W, b, item2);

    // 2) Main gather + dot kernel. Table 129,536 B + staging 8,192 B smem.
    int smem_bytes = NE * 8 * (int)sizeof(uint4) + 32 * 32 * (int)sizeof(int2);
    cudaFuncSetAttribute(mf_main_kernel,
                         cudaFuncAttributeMaxDynamicSharedMemorySize, smem_bytes);
    mf_main_kernel<<<152, 1024, smem_bytes>>>(
        dow, tim, sex, age, month, day, dest, out, n);
}

// round 11
// speedup vs baseline: 1.2142x; 1.0504x over previous
#include <cuda_runtime.h>
#include <cuda_fp16.h>

#define N_T1 168            // dow(7) * sex(2) * month(12)
#define N_T2 744            // time(24) * day(31)
#define N_T3 100            // age
#define NE   (N_T1 + N_T2 + N_T3)   // 1012
#define NUM_DEST 100000

// Pre-projected fused tables in fp16, DUPLICATED per entry:
// entry e occupies 128 B: copy A at [e*128, e*128+64)    -> smem banks 0..15
//                         copy B at [e*128+64, e*128+128) -> smem banks 16..31
__device__ uint4 g_projh[NE * 8];        // NE * 128 B
// Item table converted to fp16: row = 32 halves = 64 B = 4 uint4.
__device__ uint4 g_itemh[NUM_DEST * 4];  // 6.4 MB

// Fused prep kernel: blocks [0, CV_BLOCKS) convert the item table (bandwidth-
// bound, float4-wide), blocks [CV_BLOCKS, ...) build the projected tables.
#define CV_THREADS (NUM_DEST * 8)            // one thread per 4 floats
#define CV_BLOCKS  ((CV_THREADS + 255) / 256)
#define PRE_THREADS (NE * 32)
#define PRE_BLOCKS ((PRE_THREADS + 255) / 256)

__global__ __launch_bounds__(256)
void prep_kernel(const float* __restrict__ emb_dow,
                 const float* __restrict__ emb_time,
                 const float* __restrict__ emb_sex,
                 const float* __restrict__ emb_age,
                 const float* __restrict__ emb_month,
                 const float* __restrict__ emb_day,
                 const float* __restrict__ W,
                 const float* __restrict__ b,
                 const float4* __restrict__ item4f) {
    if (blockIdx.x < CV_BLOCKS) {
        // ---- Item table fp32 -> fp16 (one thread per float4) ----
        int t = blockIdx.x * 256 + threadIdx.x;
        if (t >= CV_THREADS) return;
        float4 f = item4f[t];
        __half2 lo = __floats2half2_rn(f.x, f.y);
        __half2 hi = __floats2half2_rn(f.z, f.w);
        reinterpret_cast<uint2*>(g_itemh)[t] =
            make_uint2(*reinterpret_cast<uint*>(&lo), *reinterpret_cast<uint*>(&hi));
        return;
    }
    // ---- Pre-projected fused user tables ----
    int t = (blockIdx.x - CV_BLOCKS) * 256 + threadIdx.x;
    if (t >= PRE_THREADS) return;
    int e = t >> 5;
    int f = t & 31;
    float v = 0.f;
    // W row layout follows concat order: dow[0:4) time[4:8) sex[8:12) age[12:16) month[16:20) day[20:24)
    if (e < N_T1) {
        int d = e / 24, rem = e % 24;
        int s = rem / 12, m = rem % 12;
        #pragma unroll
        for (int j = 0; j < 4; j++) {
            v = fmaf(emb_dow[d * 4 + j],   W[(0 + j) * 32 + f], v);
            v = fmaf(emb_sex[s * 4 + j],   W[(8 + j) * 32 + f], v);
            v = fmaf(emb_month[m * 4 + j], W[(16 + j) * 32 + f], v);
        }
    } else if (e < N_T1 + N_T2) {
        int e2 = e - N_T1;
        int tm = e2 / 31, dy = e2 % 31;
        #pragma unroll
        for (int j = 0; j < 4; j++) {
            v = fmaf(emb_time[tm * 4 + j], W[(4 + j) * 32 + f], v);
            v = fmaf(emb_day[dy * 4 + j],  W[(20 + j) * 32 + f], v);
        }
    } else {
        int a = e - (N_T1 + N_T2);
        v = b[f];
        #pragma unroll
        for (int j = 0; j < 4; j++)
            v = fmaf(emb_age[a * 4 + j], W[(12 + j) * 32 + f], v);
    }
    __half hv = __float2half_rn(v);
    __half* base = reinterpret_cast<__half*>(g_projh) + e * 64;
    base[f]      = hv;   // copy A
    base[32 + f] = hv;   // copy B
}

__global__ __launch_bounds__(1024, 1)
void mf_main_kernel(const int* __restrict__ dow,
                    const int* __restrict__ tim,
                    const int* __restrict__ sex,
                    const int* __restrict__ age,
                    const int* __restrict__ month,
                    const int* __restrict__ day,
                    const int* __restrict__ dest,
                    float* __restrict__ out,
                    int n) {
    extern __shared__ uint4 sp[];   // table (NE*8 uint4) + per-warp idx staging
    int2* stage = reinterpret_cast<int2*>(sp + NE * 8);   // 32 warps x 32 int2 = 8 KB

    for (int i = threadIdx.x; i < NE * 8; i += blockDim.x)
        sp[i] = g_projh[i];
    __syncthreads();

    const char* spb = reinterpret_cast<const char*>(sp);

    const int lane = threadIdx.x & 31;
    const int warp = threadIdx.x >> 5;
    const int sub  = lane & 3;        // position within 4-lane group (8 halves each)
    const int grp  = lane >> 2;       // group id 0..7 (contiguous lanes)
    // Dup tables: adjacent groups have opposite parity -> each 8-lane LDS phase
    // hits disjoint bank halves: deterministically conflict-free.
    const int par  = (grp & 1) * 64 + sub * 16;

    int2* stw = stage + warp * 32;    // this warp's staging slots

    const int warpsTotal = gridDim.x * (blockDim.x >> 5);
    const int gwarp = blockIdx.x * (blockDim.x >> 5) + warp;

    const __half2 zero2 = __float2half2_rn(0.f);

    for (int base = gwarp * 32; base < n; base += warpsTotal * 32) {
        // Phase A: coalesced per-lane index loads; pack + stage to smem.
        int r = base + lane;
        int pk = 0, dd = 0;
        if (r < n) {
            int i1 = dow[r] * 24 + sex[r] * 12 + month[r];   // 0..167  (8 bits)
            int t2 = tim[r] * 31 + day[r];                   // 0..743  (10 bits)
            int a3 = age[r];                                 // 0..99   (7 bits)
            pk = i1 | (t2 << 8) | (a3 << 18);
            dd = dest[r];
        }
        stw[lane] = make_int2(pk, dd);
        __syncwarp();

        // Batched broadcast reads: all 4 steps' (pk, dd) at once (no chains).
        int2 sd0 = stw[0 * 8 + grp];
        int2 sd1 = stw[1 * 8 + grp];
        int2 sd2 = stw[2 * 8 + grp];
        int2 sd3 = stw[3 * 8 + grp];

        // Batched item loads: 4 independent LDGs in flight (MLP=4).
        uint4 V0 = __ldg(&g_itemh[(size_t)sd0.y * 4 + sub]);
        uint4 V1 = __ldg(&g_itemh[(size_t)sd1.y * 4 + sub]);
        uint4 V2 = __ldg(&g_itemh[(size_t)sd2.y * 4 + sub]);
        uint4 V3 = __ldg(&g_itemh[(size_t)sd3.y * 4 + sub]);

        int pks[4] = {sd0.x, sd1.x, sd2.x, sd3.x};
        uint4 Vs[4] = {V0, V1, V2, V3};

        // Phase B: 4 sub-iterations; each processes 8 rows with 4 lanes/row.
        #pragma unroll
        for (int s = 0; s < 4; s++) {
            int j1 = pks[s] & 255;
            int j2 = N_T1 + ((pks[s] >> 8) & 1023);
            int j3 = N_T1 + N_T2 + ((pks[s] >> 18) & 127);

            // Table entries: each lane reads 16 B (8 halves); conflict-free.
            uint4 A = *reinterpret_cast<const uint4*>(spb + j1 * 128 + par);
            uint4 C = *reinterpret_cast<const uint4*>(spb + j2 * 128 + par);
            uint4 E = *reinterpret_cast<const uint4*>(spb + j3 * 128 + par);

            const __half2* a2 = reinterpret_cast<const __half2*>(&A);
            const __half2* c2 = reinterpret_cast<const __half2*>(&C);
            const __half2* e2 = reinterpret_cast<const __half2*>(&E);
            const __half2* v2 = reinterpret_cast<const __half2*>(&Vs[s]);

            // Two independent fp16 accumulators; each half accumulates only
            // TWO products (bounded rounding error), final combine in fp32.
            __half2 acc0 = zero2, acc1 = zero2;
            {
                __half2 u0 = __hadd2(__hadd2(a2[0], c2[0]), e2[0]);
                acc0 = __hfma2(u0, v2[0], acc0);
                __half2 u1 = __hadd2(__hadd2(a2[1], c2[1]), e2[1]);
                acc1 = __hfma2(u1, v2[1], acc1);
                __half2 u2 = __hadd2(__hadd2(a2[2], c2[2]), e2[2]);
                acc0 = __hfma2(u2, v2[2], acc0);
                __half2 u3 = __hadd2(__hadd2(a2[3], c2[3]), e2[3]);
                acc1 = __hfma2(u3, v2[3], acc1);
            }
            float2 fa = __half22float2(acc0);
            float2 fb = __half22float2(acc1);
            float p = (fa.x + fa.y) + (fb.x + fb.y);

            // Reduce across the 4-lane group (contiguous lanes) in fp32.
            p += __shfl_xor_sync(0xffffffffu, p, 2);
            p += __shfl_xor_sync(0xffffffffu, p, 1);

            int row = base + s * 8 + grp;
            if (sub == 0 && row < n)
                out[row] = p;     // 8 consecutive rows per step: 1 wavefront
        }
    }
}

extern "C" void kernel_launch(void* const* d_in, const int* in_sizes, int n_in,
                              void* d_out, int out_size) {
    // Input order: dayofweek, time, sex, age, month, day, destination,
    // emb_dow, emb_time, emb_sex, emb_age, emb_month, emb_day, W, b, item_table
    const int* dow   = (const int*)d_in[0];
    const int* tim   = (const int*)d_in[1];
    const int* sex   = (const int*)d_in[2];
    const int* age   = (const int*)d_in[3];
    const int* month = (const int*)d_in[4];
    const int* day   = (const int*)d_in[5];
    const int* dest  = (const int*)d_in[6];
    const float* emb_dow   = (const float*)d_in[7];
    const float* emb_time  = (const float*)d_in[8];
    const float* emb_sex   = (const float*)d_in[9];
    const float* emb_age   = (const float*)d_in[10];
    const float* emb_month = (const float*)d_in[11];
    const float* emb_day   = (const float*)d_in[12];
    const float* W = (const float*)d_in[13];
    const float* b = (const float*)d_in[14];
    const float4* item4f = (const float4*)d_in[15];
    float* out = (float*)d_out;
    int n = in_sizes[0];

    // 1) Fused prep: item fp16 conversion + projected-table build, one launch.
    prep_kernel<<<CV_BLOCKS + PRE_BLOCKS, 256>>>(
        emb_dow, emb_time, emb_sex, emb_age, emb_month, emb_day, W, b, item4f);

    // 2) Main gather + dot kernel. Table 129,536 B + staging 8,192 B smem.
    int smem_bytes = NE * 8 * (int)sizeof(uint4) + 32 * 32 * (int)sizeof(int2);
    cudaFuncSetAttribute(mf_main_kernel,
                         cudaFuncAttributeMaxDynamicSharedMemorySize, smem_bytes);
    mf_main_kernel<<<152, 1024, smem_bytes>>>(
        dow, tim, sex, age, month, day, dest, out, n);
}